// round 14
// baseline (speedup 1.0000x reference)
#include <cuda_runtime.h>
#include <cuda_fp16.h>
#include <cstdint>

// Problem constants
#define NE       1024   // experts
#define NB       1024   // batch
#define NH       64     // hidden width
#define WARPS    8
#define THREADS  256
#define RPW      128    // rows per warp  (NB / WARPS)
#define ITERS    4      // iterations per warp, 2 m16 chunks (32 rows) each
#define LDA      72     // padded halves per SMEM row (144 B -> conflict-free ldmatrix)

struct Smem {
    __half   Wt[NH][LDA];              //  9216 B : Wt[o][j] = 0.5 * W2[j][o] (pre-halved)
    __half   A[WARPS][32][LDA];        // 36864 B : per-warp fp16 h tile (2 chunks)
    uint32_t bfs[8][2][32][4];         //  8192 B : B fragments [n][kspair][lane][4]
    uint4    econst[8][4];             //   512 B : {W3/2 lo, W3/2 hi, b2/2 half2, pad}
    float    w3b[4];                   //    16 B : per-quad sum of W3/2
};   // ~54.8 KB -> 3 CTAs/SM (164 KB of 228 KB)

static __device__ __forceinline__ uint32_t smem_u32(const void* p) {
    uint32_t a;
    asm("{ .reg .u64 t; cvta.to.shared.u64 t, %1; cvt.u32.u64 %0, t; }"
        : "=r"(a) : "l"(p));
    return a;
}

// h = sigmoid(4u-2) = 0.5 + 0.5*tanh(2u-1): one MUFU.TANH per 2 elements.
static __device__ __forceinline__ uint32_t sig2_h(float a, float b) {
    __half2 t = __floats2half2_rn(2.0f * a - 1.0f, 2.0f * b - 1.0f);
    uint32_t ti = *(uint32_t*)&t, to;
    asm("tanh.approx.f16x2 %0, %1;" : "=r"(to) : "r"(ti));
    __half2 th = *(__half2*)&to;
    __half2 hv = __hfma2(th, __half2half2(__float2half(0.5f)),
                             __half2half2(__float2half(0.5f)));
    return *(uint32_t*)&hv;
}

// packed epilogue tanh: (a,b) fp32 -> tanh via f16x2 -> fp32 pair (1 MUFU / 2 elems)
static __device__ __forceinline__ float2 tanh2_f16(float a, float b) {
    __half2 t = __floats2half2_rn(a, b);
    uint32_t ti = *(uint32_t*)&t, to;
    asm("tanh.approx.f16x2 %0, %1;" : "=r"(to) : "r"(ti));
    return __half22float2(*(__half2*)&to);
}

static __device__ __forceinline__ void ldsm_x4(uint32_t* r, uint32_t addr) {
    asm volatile("ldmatrix.sync.aligned.m8n8.x4.shared.b16 {%0,%1,%2,%3}, [%4];"
                 : "=r"(r[0]), "=r"(r[1]), "=r"(r[2]), "=r"(r[3]) : "r"(addr) : "memory");
}
static __device__ __forceinline__ void ldsm_x2(uint32_t& b0, uint32_t& b1,
                                               uint32_t addr) {
    asm volatile("ldmatrix.sync.aligned.m8n8.x2.shared.b16 {%0,%1}, [%2];"
                 : "=r"(b0), "=r"(b1) : "r"(addr) : "memory");
}
static __device__ __forceinline__ void mma16816(float& c0, float& c1, float& c2,
                                                float& c3, const uint32_t* a,
                                                uint32_t b0, uint32_t b1) {
    asm volatile(
        "mma.sync.aligned.m16n8k16.row.col.f32.f16.f16.f32 "
        "{%0,%1,%2,%3}, {%4,%5,%6,%7}, {%8,%9}, {%0,%1,%2,%3};"
        : "+f"(c0), "+f"(c1), "+f"(c2), "+f"(c3)
        : "r"(a[0]), "r"(a[1]), "r"(a[2]), "r"(a[3]), "r"(b0), "r"(b1));
}

// ---------------------------------------------------------------------------
// One block = one expert. Each warp iteration handles 32 rows (2 m16 chunks):
// the B fragments and epilogue constants are loaded from SMEM ONCE per n-tile
// and reused for both chunks' MMAs, halving the dominant L1 (bfs) traffic.
// ---------------------------------------------------------------------------
__global__ __launch_bounds__(THREADS, 3)
void golem_hmma_kernel(const float* __restrict__ noise,   // [E, B, H]
                       const float* __restrict__ W2,      // [E, H, H]
                       const float* __restrict__ b2,      // [E, H]
                       const float* __restrict__ W3,      // [E, H]
                       const float* __restrict__ b3,      // [E]
                       const float* __restrict__ T,       // [B]
                       const float* __restrict__ alpha,
                       const float* __restrict__ beta,
                       const float* __restrict__ bias,
                       float* __restrict__ out)           // [B,E] + [B]
{
    extern __shared__ char smem_raw_bytes[];
    Smem& s = *(Smem*)smem_raw_bytes;

    const int e   = blockIdx.x;
    const int tid = threadIdx.x;
    const int w   = tid >> 5;
    const int l   = tid & 31;

    // T_embed piggybacks on block 0
    if (e == 0) {
        float inva = __fdividef(1.0f, alpha[0]);
        float be = beta[0], bi = bias[0];
        for (int i = tid; i < NB; i += THREADS)
            out[(size_t)NB * NE + i] = inva * cosf(be * T[i] + bi);
    }

    // Stage W2[e]/2 transposed -> Wt[o][j] fp16 (pre-halved for tanh arg)
    const float* W2e = W2 + (size_t)e * NH * NH;
    for (int i = tid; i < NH * NH; i += THREADS) {
        int j = i >> 6, o = i & 63;
        s.Wt[o][j] = __float2half_rn(0.5f * W2e[i]);
    }
    // Packed epilogue constants: econst[n][quad] = {W3/2 x2 fp32, b2/2 half2}
    if (tid < 32) {
        int n = tid >> 2, q = tid & 3;
        int o = n * 8 + 2 * q;
        float pw0 = 0.5f * W3[(size_t)e * NH + o];
        float pw1 = 0.5f * W3[(size_t)e * NH + o + 1];
        __half2 bb = __floats2half2_rn(0.5f * b2[(size_t)e * NH + o],
                                       0.5f * b2[(size_t)e * NH + o + 1]);
        uint4 ec;
        ec.x = __float_as_uint(pw0);
        ec.y = __float_as_uint(pw1);
        ec.z = *(uint32_t*)&bb;
        ec.w = 0;
        s.econst[n][q] = ec;
    }
    if (tid < 4) {
        float sum = 0.0f;
        #pragma unroll
        for (int n = 0; n < 8; n++) {
            int o = n * 8 + 2 * tid;
            sum += 0.5f * (W3[(size_t)e * NH + o] + W3[(size_t)e * NH + o + 1]);
        }
        s.w3b[tid] = sum;
    }
    __syncthreads();

    // Warp 0 builds the B-fragment table (identical for every warp)
    if (w == 0) {
        const uint32_t wtBase = smem_u32(&s.Wt[0][0]);
        const uint32_t bLd = wtBase + (uint32_t)(l & 7) * (LDA * 2)
                           + (uint32_t)((l >> 3) & 1) * 16;
        #pragma unroll
        for (int n = 0; n < 8; n++)
            #pragma unroll
            for (int ks = 0; ks < 4; ks++) {
                uint32_t b0, b1;
                ldsm_x2(b0, b1, bLd + (uint32_t)n * 8 * (LDA * 2) + (uint32_t)ks * 32);
                s.bfs[n][ks >> 1][l][(ks & 1) * 2 + 0] = b0;
                s.bfs[n][ks >> 1][l][(ks & 1) * 2 + 1] = b1;
            }
    }
    __syncthreads();

    const float b3e = b3[e];

    const uint32_t aBase = smem_u32(&s.A[w][0][0]);
    const uint32_t aLd = aBase + (uint32_t)(l & 15) * (LDA * 2) + (uint32_t)(l >> 4) * 16;
    const uint4* const bfp = (const uint4*)&s.bfs[0][0][0][0] + l;

    // Coalesced convert mapping: lane l -> sub-row (l>>4), float col (l&15)*4.
    const float* nbase = noise + ((size_t)e * NB + (size_t)w * RPW) * NH;
    const float* gsrc  = nbase + (size_t)(l >> 4) * NH + (l & 15) * 4;
    uint2* const cdst = (uint2*)((__half*)&s.A[w][0][0] + (l >> 4) * LDA + (l & 15) * 4);

    #pragma unroll 1
    for (int it = 0; it < ITERS; it++) {
        __syncwarp();   // protect A tile vs previous iteration's ldmatrix

        // ---- convert 32 rows (2 chunks): 4 batches of 4 LDG.128 ----
        const float* g = gsrc + (size_t)it * 32 * NH;
        #pragma unroll
        for (int half = 0; half < 4; half++) {
            float4 v[4];
            #pragma unroll
            for (int i = 0; i < 4; i++)
                v[i] = *(const float4*)(g + (size_t)(half * 8 + 2 * i) * NH);
            #pragma unroll
            for (int i = 0; i < 4; i++) {
                uint2 pk;
                pk.x = sig2_h(v[i].x, v[i].y);
                pk.y = sig2_h(v[i].z, v[i].w);
                cdst[(size_t)(half * 8 + 2 * i) * (LDA / 4)] = pk;
            }
        }
        __syncwarp();

        // ---- A fragments: 2 chunks x 4 K-steps ----
        uint32_t a[2][4][4];
        #pragma unroll
        for (int cc = 0; cc < 2; cc++)
            #pragma unroll
            for (int ks = 0; ks < 4; ks++)
                ldsm_x4(a[cc][ks],
                        aLd + (uint32_t)cc * 16 * (LDA * 2) + (uint32_t)ks * 32);

        // ---- GEMM + packed-tanh epilogue: B/econst loaded once per n, ----
        // ---- reused for BOTH chunks (halves bfs L1 traffic).          ----
        float w3b = s.w3b[l & 3];
        float acc00 = w3b, acc01 = w3b, acc10 = w3b, acc11 = w3b;
        #pragma unroll
        for (int n = 0; n < 8; n++) {
            uint4 ec = s.econst[n][l & 3];   // quad-broadcast LDS.128
            float pw0 = __uint_as_float(ec.x);
            float pw1 = __uint_as_float(ec.y);
            float2 b2p = __half22float2(*(__half2*)&ec.z);
            uint4 bA = bfp[(n * 2 + 0) * 32];
            uint4 bB = bfp[(n * 2 + 1) * 32];
            // chunk 0
            {
                float c0 = b2p.x, c1 = b2p.y, c2 = b2p.x, c3 = b2p.y;
                mma16816(c0, c1, c2, c3, a[0][0], bA.x, bA.y);
                mma16816(c0, c1, c2, c3, a[0][1], bA.z, bA.w);
                mma16816(c0, c1, c2, c3, a[0][2], bB.x, bB.y);
                mma16816(c0, c1, c2, c3, a[0][3], bB.z, bB.w);
                float2 t01 = tanh2_f16(c0, c1);
                float2 t23 = tanh2_f16(c2, c3);
                acc00 += t01.x * pw0 + t01.y * pw1;
                acc01 += t23.x * pw0 + t23.y * pw1;
            }
            // chunk 1
            {
                float c0 = b2p.x, c1 = b2p.y, c2 = b2p.x, c3 = b2p.y;
                mma16816(c0, c1, c2, c3, a[1][0], bA.x, bA.y);
                mma16816(c0, c1, c2, c3, a[1][1], bA.z, bA.w);
                mma16816(c0, c1, c2, c3, a[1][2], bB.x, bB.y);
                mma16816(c0, c1, c2, c3, a[1][3], bB.z, bB.w);
                float2 t01 = tanh2_f16(c0, c1);
                float2 t23 = tanh2_f16(c2, c3);
                acc10 += t01.x * pw0 + t01.y * pw1;
                acc11 += t23.x * pw0 + t23.y * pw1;
            }
        }

        // quad reduce + store, both chunks
        acc00 += __shfl_xor_sync(0xffffffffu, acc00, 1);
        acc00 += __shfl_xor_sync(0xffffffffu, acc00, 2);
        acc01 += __shfl_xor_sync(0xffffffffu, acc01, 1);
        acc01 += __shfl_xor_sync(0xffffffffu, acc01, 2);
        acc10 += __shfl_xor_sync(0xffffffffu, acc10, 1);
        acc10 += __shfl_xor_sync(0xffffffffu, acc10, 2);
        acc11 += __shfl_xor_sync(0xffffffffu, acc11, 1);
        acc11 += __shfl_xor_sync(0xffffffffu, acc11, 2);

        if ((l & 3) == 0) {
            int r0 = w * RPW + it * 32 + (l >> 2);
            out[(size_t)r0 * NE + e]        = acc00 + b3e;
            out[(size_t)(r0 + 8) * NE + e]  = acc01 + b3e;
            out[(size_t)(r0 + 16) * NE + e] = acc10 + b3e;
            out[(size_t)(r0 + 24) * NE + e] = acc11 + b3e;
        }
    }
}

// ---------------------------------------------------------------------------
// kernel_launch — inputs: 0:T 1:noise 2:W1(dead) 3:W2 4:b2 5:W3 6:b3
//                          7:alpha 8:beta 9:bias.  Output fp32: B_mat[B,E] + T_embed[B]
// ---------------------------------------------------------------------------
extern "C" void kernel_launch(void* const* d_in, const int* in_sizes, int n_in,
                              void* d_out, int out_size)
{
    const float* T     = (const float*)d_in[0];
    const float* noise = (const float*)d_in[1];
    const float* W2    = (const float*)d_in[3];
    const float* b2    = (const float*)d_in[4];
    const float* W3    = (const float*)d_in[5];
    const float* b3    = (const float*)d_in[6];
    const float* alpha = (const float*)d_in[7];
    const float* beta  = (const float*)d_in[8];
    const float* bias  = (const float*)d_in[9];

    cudaFuncSetAttribute(golem_hmma_kernel,
                         cudaFuncAttributeMaxDynamicSharedMemorySize,
                         (int)sizeof(Smem));
    golem_hmma_kernel<<<NE, THREADS, sizeof(Smem)>>>(noise, W2, b2, W3, b3,
                                                     T, alpha, beta, bias,
                                                     (float*)d_out);
}

// round 15
// speedup vs baseline: 1.7084x; 1.7084x over previous
#include <cuda_runtime.h>
#include <cuda_fp16.h>
#include <cstdint>

// Problem constants
#define NE       1024   // experts
#define NB       1024   // batch
#define NH       64     // hidden width
#define WARPS    8
#define THREADS  256
#define RPW      128    // rows per warp  (NB / WARPS)
#define CHUNKS   8      // m16 chunks per warp (RPW / 16)
#define LDA      72     // padded halves per SMEM row (144 B -> conflict-free ldmatrix)

struct Smem {
    __half   Wt[NH][LDA];              //  9216 B : Wt[o][j] = 0.5 * W2[j][o] (pre-halved)
    __half   A[WARPS][16][LDA];        // 18432 B : per-warp fp16 h tile
    uint32_t bfs[8][2][32][4];         //  8192 B : B fragments [n][kspair][lane][4]
    uint4    econst[8][4];             //   512 B : {W3/2 lo, W3/2 hi, b2/2 half2, pad}
    float    w3b[4];                   //    16 B : per-quad sum of W3/2
};   // ~36.4 KB -> 4 CTAs/SM

static __device__ __forceinline__ uint32_t smem_u32(const void* p) {
    uint32_t a;
    asm("{ .reg .u64 t; cvta.to.shared.u64 t, %1; cvt.u32.u64 %0, t; }"
        : "=r"(a) : "l"(p));
    return a;
}

// h = sigmoid(4u-2) = 0.5 + 0.5*tanh(2u-1): one MUFU.TANH per 2 elements.
static __device__ __forceinline__ uint32_t sig2_h(float a, float b) {
    __half2 t = __floats2half2_rn(2.0f * a - 1.0f, 2.0f * b - 1.0f);
    uint32_t ti = *(uint32_t*)&t, to;
    asm("tanh.approx.f16x2 %0, %1;" : "=r"(to) : "r"(ti));
    __half2 th = *(__half2*)&to;
    __half2 hv = __hfma2(th, __half2half2(__float2half(0.5f)),
                             __half2half2(__float2half(0.5f)));
    return *(uint32_t*)&hv;
}

// fp32 tanh.approx (1 MUFU) for the epilogue sigmoid — no pack/unpack chain
static __device__ __forceinline__ float tanhf_approx(float x) {
    float y;
    asm("tanh.approx.f32 %0, %1;" : "=f"(y) : "f"(x));
    return y;
}

static __device__ __forceinline__ void ldsm_x4(uint32_t* r, uint32_t addr) {
    asm volatile("ldmatrix.sync.aligned.m8n8.x4.shared.b16 {%0,%1,%2,%3}, [%4];"
                 : "=r"(r[0]), "=r"(r[1]), "=r"(r[2]), "=r"(r[3]) : "r"(addr) : "memory");
}
static __device__ __forceinline__ void ldsm_x2(uint32_t& b0, uint32_t& b1,
                                               uint32_t addr) {
    asm volatile("ldmatrix.sync.aligned.m8n8.x2.shared.b16 {%0,%1}, [%2];"
                 : "=r"(b0), "=r"(b1) : "r"(addr) : "memory");
}
static __device__ __forceinline__ void mma16816(float& c0, float& c1, float& c2,
                                                float& c3, const uint32_t* a,
                                                uint32_t b0, uint32_t b1) {
    asm volatile(
        "mma.sync.aligned.m16n8k16.row.col.f32.f16.f16.f32 "
        "{%0,%1,%2,%3}, {%4,%5,%6,%7}, {%8,%9}, {%0,%1,%2,%3};"
        : "+f"(c0), "+f"(c1), "+f"(c2), "+f"(c3)
        : "r"(a[0]), "r"(a[1]), "r"(a[2]), "r"(a[3]), "r"(b0), "r"(b1));
}

// ---------------------------------------------------------------------------
// One block = one expert (R12 structure: the proven 4-CTA/SM optimum).
// Per-expert constants in SMEM -> <=64 regs. Convert reads noise directly
// with coalesced streaming LDG.128 (4 lines/LDG). Epilogue uses fp32 tanh
// (4 MUFU + 4 FFMA per n-tile, no f16 pack/unpack chain).
// ---------------------------------------------------------------------------
__global__ __launch_bounds__(THREADS, 4)
void golem_hmma_kernel(const float* __restrict__ noise,   // [E, B, H]
                       const float* __restrict__ W2,      // [E, H, H]
                       const float* __restrict__ b2,      // [E, H]
                       const float* __restrict__ W3,      // [E, H]
                       const float* __restrict__ b3,      // [E]
                       const float* __restrict__ T,       // [B]
                       const float* __restrict__ alpha,
                       const float* __restrict__ beta,
                       const float* __restrict__ bias,
                       float* __restrict__ out)           // [B,E] + [B]
{
    extern __shared__ char smem_raw_bytes[];
    Smem& s = *(Smem*)smem_raw_bytes;

    const int e   = blockIdx.x;
    const int tid = threadIdx.x;
    const int w   = tid >> 5;
    const int l   = tid & 31;

    // T_embed piggybacks on block 0
    if (e == 0) {
        float inva = __fdividef(1.0f, alpha[0]);
        float be = beta[0], bi = bias[0];
        for (int i = tid; i < NB; i += THREADS)
            out[(size_t)NB * NE + i] = inva * cosf(be * T[i] + bi);
    }

    // Stage W2[e]/2 transposed -> Wt[o][j] fp16 (pre-halved for tanh arg)
    const float* W2e = W2 + (size_t)e * NH * NH;
    for (int i = tid; i < NH * NH; i += THREADS) {
        int j = i >> 6, o = i & 63;
        s.Wt[o][j] = __float2half_rn(0.5f * W2e[i]);
    }
    // Packed epilogue constants: econst[n][quad] = {W3/2 x2 fp32, b2/2 half2}
    if (tid < 32) {
        int n = tid >> 2, q = tid & 3;
        int o = n * 8 + 2 * q;
        float pw0 = 0.5f * W3[(size_t)e * NH + o];
        float pw1 = 0.5f * W3[(size_t)e * NH + o + 1];
        __half2 bb = __floats2half2_rn(0.5f * b2[(size_t)e * NH + o],
                                       0.5f * b2[(size_t)e * NH + o + 1]);
        uint4 ec;
        ec.x = __float_as_uint(pw0);
        ec.y = __float_as_uint(pw1);
        ec.z = *(uint32_t*)&bb;
        ec.w = 0;
        s.econst[n][q] = ec;
    }
    if (tid < 4) {
        float sum = 0.0f;
        #pragma unroll
        for (int n = 0; n < 8; n++) {
            int o = n * 8 + 2 * tid;
            sum += 0.5f * (W3[(size_t)e * NH + o] + W3[(size_t)e * NH + o + 1]);
        }
        s.w3b[tid] = sum;
    }
    __syncthreads();

    // Warp 0 builds the B-fragment table (identical for every warp)
    if (w == 0) {
        const uint32_t wtBase = smem_u32(&s.Wt[0][0]);
        const uint32_t bLd = wtBase + (uint32_t)(l & 7) * (LDA * 2)
                           + (uint32_t)((l >> 3) & 1) * 16;
        #pragma unroll
        for (int n = 0; n < 8; n++)
            #pragma unroll
            for (int ks = 0; ks < 4; ks++) {
                uint32_t b0, b1;
                ldsm_x2(b0, b1, bLd + (uint32_t)n * 8 * (LDA * 2) + (uint32_t)ks * 32);
                s.bfs[n][ks >> 1][l][(ks & 1) * 2 + 0] = b0;
                s.bfs[n][ks >> 1][l][(ks & 1) * 2 + 1] = b1;
            }
    }
    __syncthreads();

    const float b3e = b3[e];
    const float w3b = s.w3b[l & 3];   // loop-invariant: hoisted past asm barriers

    const uint32_t aBase = smem_u32(&s.A[w][0][0]);
    const uint32_t aLd = aBase + (uint32_t)(l & 15) * (LDA * 2) + (uint32_t)(l >> 4) * 16;
    const uint4* const bfp = (const uint4*)&s.bfs[0][0][0][0] + l;

    // Coalesced convert mapping: lane l -> sub-row (l>>4), float col (l&15)*4.
    // LDG.128 i covers rows {2i, 2i+1}: 512B contiguous = 4 lines per LDG.
    const float* nbase = noise + ((size_t)e * NB + (size_t)w * RPW) * NH;
    const float4* gsrc = (const float4*)(nbase + (size_t)(l >> 4) * NH) + (l & 15);
    uint2* const cdst = (uint2*)((__half*)&s.A[w][0][0] + (l >> 4) * LDA + (l & 15) * 4);

    #pragma unroll 1
    for (int ch = 0; ch < CHUNKS; ch++) {
        __syncwarp();   // protect A tile vs previous chunk's ldmatrix

        // ---- convert 16 rows: streaming LDG, two batches of 4 (MLP=4) ----
        const float4* g = gsrc + (size_t)ch * 16 * (NH / 4);
        {
            float4 v[4];
            #pragma unroll
            for (int i = 0; i < 4; i++)
                v[i] = __ldcs(g + (size_t)(2 * i) * (NH / 4));
            #pragma unroll
            for (int i = 0; i < 4; i++) {
                uint2 pk;
                pk.x = sig2_h(v[i].x, v[i].y);
                pk.y = sig2_h(v[i].z, v[i].w);
                cdst[(size_t)(2 * i) * (LDA / 4)] = pk;
            }
        }
        {
            float4 v[4];
            #pragma unroll
            for (int i = 0; i < 4; i++)
                v[i] = __ldcs(g + (size_t)(8 + 2 * i) * (NH / 4));
            #pragma unroll
            for (int i = 0; i < 4; i++) {
                uint2 pk;
                pk.x = sig2_h(v[i].x, v[i].y);
                pk.y = sig2_h(v[i].z, v[i].w);
                cdst[(size_t)(8 + 2 * i) * (LDA / 4)] = pk;
            }
        }
        __syncwarp();

        // ---- A fragments: 4 K-steps ----
        uint32_t a[4][4];
        #pragma unroll
        for (int ks = 0; ks < 4; ks++)
            ldsm_x4(a[ks], aLd + (uint32_t)ks * 32);

        // ---- GEMM + fp32-tanh epilogue (B + constants from SMEM) ----
        float acc0 = w3b, acc1 = w3b;
        #pragma unroll
        for (int n = 0; n < 8; n++) {
            uint4 ec = s.econst[n][l & 3];   // quad-broadcast LDS.128
            float pw0 = __uint_as_float(ec.x);
            float pw1 = __uint_as_float(ec.y);
            float2 b2p = __half22float2(*(__half2*)&ec.z);
            float c0 = b2p.x, c1 = b2p.y, c2 = b2p.x, c3 = b2p.y;
            uint4 bA = bfp[(n * 2 + 0) * 32];
            uint4 bB = bfp[(n * 2 + 1) * 32];
            mma16816(c0, c1, c2, c3, a[0], bA.x, bA.y);
            mma16816(c0, c1, c2, c3, a[1], bA.z, bA.w);
            mma16816(c0, c1, c2, c3, a[2], bB.x, bB.y);
            mma16816(c0, c1, c2, c3, a[3], bB.z, bB.w);
            acc0 += tanhf_approx(c0) * pw0 + tanhf_approx(c1) * pw1;
            acc1 += tanhf_approx(c2) * pw0 + tanhf_approx(c3) * pw1;
        }

        // quad reduce over (l&3)
        acc0 += __shfl_xor_sync(0xffffffffu, acc0, 1);
        acc0 += __shfl_xor_sync(0xffffffffu, acc0, 2);
        acc1 += __shfl_xor_sync(0xffffffffu, acc1, 1);
        acc1 += __shfl_xor_sync(0xffffffffu, acc1, 2);

        if ((l & 3) == 0) {
            int r = w * RPW + ch * 16 + (l >> 2);
            out[(size_t)r * NE + e]       = acc0 + b3e;
            out[(size_t)(r + 8) * NE + e] = acc1 + b3e;
        }
    }
}

// ---------------------------------------------------------------------------
// kernel_launch — inputs: 0:T 1:noise 2:W1(dead) 3:W2 4:b2 5:W3 6:b3
//                          7:alpha 8:beta 9:bias.  Output fp32: B_mat[B,E] + T_embed[B]
// ---------------------------------------------------------------------------
extern "C" void kernel_launch(void* const* d_in, const int* in_sizes, int n_in,
                              void* d_out, int out_size)
{
    const float* T     = (const float*)d_in[0];
    const float* noise = (const float*)d_in[1];
    const float* W2    = (const float*)d_in[3];
    const float* b2    = (const float*)d_in[4];
    const float* W3    = (const float*)d_in[5];
    const float* b3    = (const float*)d_in[6];
    const float* alpha = (const float*)d_in[7];
    const float* beta  = (const float*)d_in[8];
    const float* bias  = (const float*)d_in[9];

    cudaFuncSetAttribute(golem_hmma_kernel,
                         cudaFuncAttributeMaxDynamicSharedMemorySize,
                         (int)sizeof(Smem));
    golem_hmma_kernel<<<NE, THREADS, sizeof(Smem)>>>(noise, W2, b2, W3, b3,
                                                     T, alpha, beta, bias,
                                                     (float*)d_out);
}